// round 15
// baseline (speedup 1.0000x reference)
#include <cuda_runtime.h>
#include <math.h>

#define B 64
#define CHI 20
#define D 65536                  // 64*32*32 floats per frame
#define BPB 64                   // blocks per batch
#define DPB (D / BPB)            // 1024 d's per block
#define SLICE (DPB * CHI)        // 20480 floats = 81920 bytes per block slice
#define SLICE4 (SLICE / 4)       // 5120 float4
#define CONC 4                   // concurrent batch groups
#define NITER (B / CONC)         // 16 iterations
#define NBLK (CONC * BPB)        // 256 blocks; 2/SM capacity -> all co-resident
#define THREADS 256
#define DPT (DPB / THREADS)      // 4 d's per thread

__device__ float g_partial[B * BPB * CHI];   // per-block dot partials [b][j][c]
__device__ unsigned g_bar[CONC * NITER];

__global__ void init_kernel() {
    if (threadIdx.x < CONC * NITER) g_bar[threadIdx.x] = 0u;
}

// ---------------------------------------------------------------------------
// Fused kernel, SMEM-resident slices. Group g (64 blocks) processes batches
// b = it*CONC + g. Per iteration:
//   stage:   coalesced DRAM read of the block's contiguous 81.92 KB slice
//            (d-major rows x[d, 0..19] for 1024 d's -- holds BOTH operands)
//   phase 1: dots acc[c] += x[d,c] * x[d,19] for all 20 c, from SMEM
//   barrier + softmax (tiny, L2-hot partials)
//   phase 2: out[b,d] = sum_c x[d,c] * alpha[c], same SMEM rows
// x is read from DRAM exactly once. 352 MB total DRAM traffic.
// ---------------------------------------------------------------------------
__global__ __launch_bounds__(THREADS) void fused_kernel(const float* __restrict__ x,
                                                        float* __restrict__ out) {
    extern __shared__ float4 s4[];          // SLICE4 float4 = 81920 B
    __shared__ float sred[CHI][8];
    __shared__ float s_alpha[CHI];

    const int g    = blockIdx.x / BPB;      // group (concurrent batch slot)
    const int j    = blockIdx.x % BPB;      // block within group
    const int tid  = threadIdx.x;
    const int warp = tid >> 5;
    const int lane = tid & 31;
    const float* s_f = reinterpret_cast<const float*>(s4);

    for (int it = 0; it < NITER; it++) {
        const int b = it * CONC + g;

        // ---------------- stage slice (coalesced, batched for MLP) ----------
        const float4* __restrict__ src = reinterpret_cast<const float4*>(
            x + (size_t)b * CHI * D + (size_t)j * SLICE);
        #pragma unroll
        for (int grp = 0; grp < 4; grp++) {     // 4 groups of 5 loads in flight
            float4 t[5];
            #pragma unroll
            for (int u = 0; u < 5; u++)
                t[u] = src[(grp * 5 + u) * THREADS + tid];
            #pragma unroll
            for (int u = 0; u < 5; u++)
                s4[(grp * 5 + u) * THREADS + tid] = t[u];
        }
        __syncthreads();

        // ---------------- phase 1: all-c dots from SMEM ----------------------
        float acc[CHI];
        #pragma unroll
        for (int c = 0; c < CHI; c++) acc[c] = 0.0f;

        #pragma unroll
        for (int k = 0; k < DPT; k++) {
            const int ld = k * THREADS + tid;           // local d
            const float4* row = s4 + (size_t)ld * 5;    // 20 floats, 80B stride
            const float4 r0 = row[0], r1 = row[1], r2 = row[2],
                         r3 = row[3], r4 = row[4];
            const float last = r4.w;
            acc[0]  = fmaf(r0.x, last, acc[0]);
            acc[1]  = fmaf(r0.y, last, acc[1]);
            acc[2]  = fmaf(r0.z, last, acc[2]);
            acc[3]  = fmaf(r0.w, last, acc[3]);
            acc[4]  = fmaf(r1.x, last, acc[4]);
            acc[5]  = fmaf(r1.y, last, acc[5]);
            acc[6]  = fmaf(r1.z, last, acc[6]);
            acc[7]  = fmaf(r1.w, last, acc[7]);
            acc[8]  = fmaf(r2.x, last, acc[8]);
            acc[9]  = fmaf(r2.y, last, acc[9]);
            acc[10] = fmaf(r2.z, last, acc[10]);
            acc[11] = fmaf(r2.w, last, acc[11]);
            acc[12] = fmaf(r3.x, last, acc[12]);
            acc[13] = fmaf(r3.y, last, acc[13]);
            acc[14] = fmaf(r3.z, last, acc[14]);
            acc[15] = fmaf(r3.w, last, acc[15]);
            acc[16] = fmaf(r4.x, last, acc[16]);
            acc[17] = fmaf(r4.y, last, acc[17]);
            acc[18] = fmaf(r4.z, last, acc[18]);
            acc[19] = fmaf(r4.w, last, acc[19]);
        }

        #pragma unroll
        for (int c = 0; c < CHI; c++) {
            #pragma unroll
            for (int o = 16; o; o >>= 1)
                acc[c] += __shfl_xor_sync(0xFFFFFFFFu, acc[c], o);
        }
        if (lane == 0) {
            #pragma unroll
            for (int c = 0; c < CHI; c++) sred[c][warp] = acc[c];
        }
        __syncthreads();
        if (tid < CHI) {
            float v = 0.0f;
            #pragma unroll
            for (int w = 0; w < 8; w++) v += sred[tid][w];
            g_partial[((size_t)b * BPB + j) * CHI + tid] = v;
        }
        __threadfence();                     // release partials
        __syncthreads();

        // ---------------- group barrier (all blocks resident) ----------------
        if (tid == 0) {
            unsigned* ctr = &g_bar[g * NITER + it];
            atomicAdd(ctr, 1u);
            while (*(volatile unsigned*)ctr < (unsigned)BPB) __nanosleep(64);
            __threadfence();                 // acquire
        }
        __syncthreads();

        // ---------------- softmax (warp 0) -----------------------------------
        if (warp == 0) {
            float s = -INFINITY;
            if (lane < CHI) {
                float t = 0.0f;
                const float* p = &g_partial[(size_t)b * BPB * CHI + lane];
                #pragma unroll 8
                for (int jj = 0; jj < BPB; jj++) t += p[jj * CHI];
                s = t * (1.0f / CHI);
            }
            float m = s;
            #pragma unroll
            for (int o = 16; o; o >>= 1)
                m = fmaxf(m, __shfl_xor_sync(0xFFFFFFFFu, m, o));
            float e = (lane < CHI) ? expf(s - m) : 0.0f;
            float sum = e;
            #pragma unroll
            for (int o = 16; o; o >>= 1)
                sum += __shfl_xor_sync(0xFFFFFFFFu, sum, o);
            if (lane < CHI) s_alpha[lane] = e / sum;
        }
        __syncthreads();

        float a[CHI];
        #pragma unroll
        for (int c = 0; c < CHI; c++) a[c] = s_alpha[c];

        // ---------------- phase 2: weighted sum from same SMEM rows ----------
        #pragma unroll
        for (int k = 0; k < DPT; k++) {
            const int ld = k * THREADS + tid;
            const float4* row = s4 + (size_t)ld * 5;
            float v = 0.0f;
            #pragma unroll
            for (int i = 0; i < 5; i++) {
                const float4 r = row[i];
                v = fmaf(r.x, a[4 * i + 0], fmaf(r.y, a[4 * i + 1],
                    fmaf(r.z, a[4 * i + 2], fmaf(r.w, a[4 * i + 3], v))));
            }
            out[(size_t)b * D + j * DPB + ld] = v;
        }
        __syncthreads();        // slice consumed; safe to restage next iter
    }
}

extern "C" void kernel_launch(void* const* d_in, const int* in_sizes, int n_in,
                              void* d_out, int out_size) {
    const float* x = (const float*)d_in[0];
    float* out = (float*)d_out;

    static bool attr_set = false;
    if (!attr_set) {
        cudaFuncSetAttribute(fused_kernel,
                             cudaFuncAttributeMaxDynamicSharedMemorySize,
                             SLICE4 * (int)sizeof(float4));
        attr_set = true;
    }

    init_kernel<<<1, 64>>>();
    fused_kernel<<<NBLK, THREADS, SLICE4 * sizeof(float4)>>>(x, out);
}